// round 4
// baseline (speedup 1.0000x reference)
#include <cuda_runtime.h>
#include <cstdint>

// MaskLayer: per-(batch,channel) spatial argmax -> L1-distance mask -> scale.
// x, out: [B, 14, 14, 512] float32, channel-innermost.
//
// One CTA = (one batch, 128-channel tile). 196x128 floats (100,352 B) staged
// in dynamic smem via cp.async (single DRAM read), per-channel row/col argmax
// reduced from smem, mask applied from smem, STG.128 coalesced stores.
// 2 CTAs/SM so one CTA's DRAM fill overlaps another's compute.

static constexpr int IMGS     = 14;
static constexpr int SPATIAL  = IMGS * IMGS;            // 196
static constexpr int DEPTH    = 512;
static constexpr int DTILE    = 128;
static constexpr int BLOCK    = 128;
static constexpr int VECS     = SPATIAL * DTILE / 4;    // 6272 float4 per tile
static constexpr int ITERS    = VECS / BLOCK;           // 49
static constexpr int SMEM_BYTES = SPATIAL * DTILE * (int)sizeof(float);  // 100352

static constexpr float NEG_BIG = -3.402823466e38f;

__device__ __forceinline__ uint32_t smem_u32(const void* p) {
    return (uint32_t)__cvta_generic_to_shared(p);
}

__global__ void __launch_bounds__(BLOCK, 2)
mask_layer_kernel(const float* __restrict__ x, float* __restrict__ out) {
    extern __shared__ float tile[];        // [SPATIAL][DTILE]
    __shared__ int sidx[DTILE];            // packed (row | col<<16) per channel

    const int tid = threadIdx.x;
    const int dt  = blockIdx.x & 3;        // DEPTH / DTILE = 4 tiles per batch
    const int b   = blockIdx.x >> 2;
    const size_t base = (size_t)b * (SPATIAL * DEPTH) + (size_t)dt * DTILE;
    const float* __restrict__ src = x + base;

    // ---- Phase A: stage tile into smem with cp.async (16B, L1-bypass) ----
    // idx -> (s = idx>>5 spatial, c4 = (idx&31)*4 channel). Warp covers 512
    // contiguous bytes of gmem per iteration; smem stores conflict-free.
#pragma unroll
    for (int k = 0; k < ITERS; k++) {
        int idx = tid + k * BLOCK;
        int s   = idx >> 5;
        int c4  = (idx & 31) << 2;
        uint32_t dst = smem_u32(tile + s * DTILE + c4);
        const float* g = src + (size_t)s * DEPTH + c4;
        asm volatile("cp.async.cg.shared.global [%0], [%1], 16;\n"
                     :: "r"(dst), "l"(g));
    }
    asm volatile("cp.async.commit_group;\ncp.async.wait_group 0;\n" ::: "memory");
    __syncthreads();

    // ---- Phase B: per-channel argmax(rowmax) / argmax(colmax) ----
    // Strict '>' with ascending index == jnp.argmax first-occurrence.
    {
        float colmax[IMGS];
#pragma unroll
        for (int j = 0; j < IMGS; j++) colmax[j] = NEG_BIG;

        float bestRow = NEG_BIG;
        int rowIdx = 0;
#pragma unroll 2
        for (int i = 0; i < IMGS; i++) {
            float rmax = NEG_BIG;
#pragma unroll
            for (int j = 0; j < IMGS; j++) {
                float v = tile[(i * IMGS + j) * DTILE + tid];   // bank = tid%32
                rmax = fmaxf(rmax, v);
                colmax[j] = fmaxf(colmax[j], v);
            }
            if (rmax > bestRow) { bestRow = rmax; rowIdx = i; }
        }
        int colIdx = 0;
        float bestCol = colmax[0];
#pragma unroll
        for (int j = 1; j < IMGS; j++) {
            if (colmax[j] > bestCol) { bestCol = colmax[j]; colIdx = j; }
        }
        sidx[tid] = rowIdx | (colIdx << 16);
    }
    __syncthreads();

    // ---- Phase C: apply mask, vectorized 16B stores ----
    const float COEF = (float)(4.0 / 14.0);     // BETA / IMG_SIZE
    const float TAUF = (float)(0.5 / 196.0);    // 0.5 / (14*14)
    float* __restrict__ dst = out + base;

#pragma unroll 7
    for (int k = 0; k < ITERS; k++) {
        int idx = tid + k * BLOCK;
        int s   = idx >> 5;
        int c4  = (idx & 31) << 2;
        int i   = s / IMGS;
        int j   = s - i * IMGS;

        float4 v = *(const float4*)(tile + s * DTILE + c4);
        int4   p = *(const int4*)(sidx + c4);

        auto msk = [&](int pk) -> float {
            int r = pk & 0xFFFF;
            int c = pk >> 16;
            int l1 = abs(i - r) + abs(j - c);
            // match JAX rounding: mul then subtract (no FMA contraction)
            float val = 1.0f - __fmul_rn(COEF, (float)l1);
            return TAUF * fmaxf(val, -1.0f);
        };

        float4 o;
        o.x = msk(p.x) * v.x;
        o.y = msk(p.y) * v.y;
        o.z = msk(p.z) * v.z;
        o.w = msk(p.w) * v.w;
        *(float4*)(dst + (size_t)s * DEPTH + c4) = o;
    }
}

extern "C" void kernel_launch(void* const* d_in, const int* in_sizes, int n_in,
                              void* d_out, int out_size) {
    (void)n_in; (void)out_size;
    const float* x = (const float*)d_in[0];
    float* out = (float*)d_out;

    int n = in_sizes[0];                       // B * 196 * 512
    int batches = n / (SPATIAL * DEPTH);       // 1024
    int grid = batches * (DEPTH / DTILE);      // 4096

    // Idempotent, deterministic on every call; executes immediately (not a
    // stream op), so graph capture is unaffected.
    cudaFuncSetAttribute(mask_layer_kernel,
                         cudaFuncAttributeMaxDynamicSharedMemorySize, SMEM_BYTES);

    mask_layer_kernel<<<grid, BLOCK, SMEM_BYTES>>>(x, out);
}